// round 13
// baseline (speedup 1.0000x reference)
#include <cuda_runtime.h>

// PWC-Net correlation (MAX_DISP=4 -> 81 channels) + LeakyReLU(0.1), /C normalize.
// feat1, feat2: [N=8, C=256, H=80, W=160] fp32. out: [N, 81, H, W] fp32.
//
// R7 persistent grid 232us. R9 occ3 224us. R10 issue diet 213us
// (crossbar 59%, fma pipe ~56%, issue 59% -> lockstep/latency residual).
// R11: warp decoupling. s2 is warp-private (warp dy writes+reads only row dy);
//      the per-phase __syncthreads existed only to publish s1. Now f1 is read
//      directly via __ldg (row is L1-resident; same L1TEX bytes), s1 removed,
//      and the phase sync is cp.async.wait_group+__syncwarp. 65 -> 2 barriers
//      per row; 27 warps/SM run self-paced. Occ-4 ruled out: RF caps regs at
//      56 for 4x288thr (45 accs/thread -> impossible).
// R12: identical resubmit of R11 (R11 hit broker infra failure, never ran).

#define MAXD 4
#define DD   9
#define NCH  81
#define C_   256
#define H_   80
#define W_   160
#define N_   8
#define HW_  (H_ * W_)
#define NROWS (N_ * H_)
#define CC   4
#define P_   5
#define F2W  (W_ + 2*MAXD)   // 168
#define NQ4  (F2W / 4)       // 42
#define NTHREADS (DD * 32)   // 288
#define NCHUNK (C_ / CC)     // 64
#define NBLOCKS (148 * 3)    // 444 persistent blocks, 3 CTAs/SM

#define S2_FLOATS (2 * CC * DD * F2W)       // 12096
#define SMEM_BYTES (S2_FLOATS * 4)          // 48384 B -> 145KB/SM at occ 3

__device__ int g_row_ctr;
__global__ void reset_ctr_kernel() { g_row_ctr = 0; }

__device__ __forceinline__ void cp16(float* dst_smem, const float* src_gmem) {
    unsigned d = (unsigned)__cvta_generic_to_shared(dst_smem);
    asm volatile("cp.async.cg.shared.global [%0], [%1], 16;" :: "r"(d), "l"(src_gmem));
}
#define CP_COMMIT() asm volatile("cp.async.commit_group;")
#define CP_WAIT0()  asm volatile("cp.async.wait_group 0;" ::: "memory")

__global__ __launch_bounds__(NTHREADS, 3)
void corr_leaky_kernel(const float* __restrict__ f1,
                       const float* __restrict__ f2,
                       float* __restrict__ out)
{
    extern __shared__ __align__(16) float s2[];   // [2][CC][DD][F2W], warp-private rows
#define S2REF(b,c,r,j) s2[(((b)*CC + (c))*DD + (r))*F2W + (j)]
    __shared__ int s_row;

    const int tid  = threadIdx.x;
    const int dy   = tid >> 5;
    const int lane = tid & 31;
    const int x0   = lane * P_;

    const float scale = 1.0f / (float)C_;

    for (;;) {
        if (tid == 0) s_row = atomicAdd(&g_row_ctr, 1);
        __syncthreads();
        const int row = s_row;       // end-of-row barrier orders next rewrite
        if (row >= NROWS) break;

        const int n = row / H_;
        const int y = row - n * H_;

        const int img_base = n * C_ * HW_;
        const int  gy    = y + dy - MAXD;
        const bool rowok = ((unsigned)gy < (unsigned)H_);
        const float* f2base = f2 + img_base + gy * W_;
        const float* f1p    = f1 + img_base + y * W_ + x0;   // walks +HW_ per channel

        float acc[P_][DD];
#pragma unroll
        for (int p = 0; p < P_; p++)
#pragma unroll
            for (int dx = 0; dx < DD; dx++) acc[p][dx] = 0.0f;

        if (rowok) {
            // pad slots (borders) of this warp's rows, both buffers
            const float4 z4 = make_float4(0.f, 0.f, 0.f, 0.f);
#pragma unroll
            for (int b = 0; b < 2; b++)
#pragma unroll
                for (int c = 0; c < CC; c++) {
                    if (lane == 0) *(float4*)&S2REF(b, c, dy, 0) = z4;
                    if (lane == 1) *(float4*)&S2REF(b, c, dy, 4 * (NQ4 - 1)) = z4;
                }
            __syncwarp();

            // prologue: prefetch chunk 0 into buffer 0 (this warp's rows only)
#pragma unroll
            for (int c = 0; c < CC; c++) {
                const float* rowp = f2base + c * HW_;
                if (lane >= 1) cp16(&S2REF(0, c, dy, 4 * lane),        rowp + 4 * lane - 4);
                if (lane <= 8) cp16(&S2REF(0, c, dy, 4 * (32 + lane)), rowp + 4 * (32 + lane) - 4);
            }
            CP_COMMIT();

#pragma unroll 2
            for (int i = 0; i < NCHUNK; i++) {
                const int cur = i & 1;           // compile-time under unroll 2
                CP_WAIT0();
                __syncwarp();                    // warp-scope publish + WAR guard

                if (i + 1 < NCHUNK) {
                    const int nb = cur ^ 1;
                    const int c0 = (i + 1) * CC;
#pragma unroll
                    for (int c = 0; c < CC; c++) {
                        const float* rowp = f2base + (c0 + c) * HW_;
                        if (lane >= 1) cp16(&S2REF(nb, c, dy, 4 * lane),        rowp + 4 * lane - 4);
                        if (lane <= 8) cp16(&S2REF(nb, c, dy, 4 * (32 + lane)), rowp + 4 * (32 + lane) - 4);
                    }
                    CP_COMMIT();
                }

                // compute: a from gmem (L1-hot row), b streamed from smem
#pragma unroll
                for (int cc = 0; cc < CC; cc++) {
                    const float* s2row = &S2REF(cur, cc, dy, x0);
                    float a[P_];
#pragma unroll
                    for (int p = 0; p < P_; p++) a[p] = __ldg(f1p + p);
                    f1p += HW_;
#pragma unroll
                    for (int k = 0; k < P_ + DD - 1; k++) {
                        const float bk = s2row[k];
                        const int plo = (k - (DD - 1)) > 0 ? (k - (DD - 1)) : 0;
                        const int phi = k < (P_ - 1) ? k : (P_ - 1);
#pragma unroll
                        for (int p = plo; p <= phi; p++)
                            acc[p][k - p] = fmaf(a[p], bk, acc[p][k - p]);
                    }
                }
            }
        }
        // !rowok warps: acc stays 0 -> leaky(0) = 0, matches zero-padded corr

        // epilogue: /C, LeakyReLU(0.1), store
        const int out_base = n * NCH * HW_ + y * W_;
#pragma unroll
        for (int dx = 0; dx < DD; dx++) {
            const int ch = dy * DD + dx;
            float* orow = out + out_base + ch * HW_;
#pragma unroll
            for (int p = 0; p < P_; p++) {
                float v = acc[p][dx] * scale;
                v = (v > 0.0f) ? v : 0.1f * v;
                orow[x0 + p] = v;
            }
        }

        __syncthreads();   // orders s_row rewrite (and smem reuse) for next row
    }
}

extern "C" void kernel_launch(void* const* d_in, const int* in_sizes, int n_in,
                              void* d_out, int out_size)
{
    const float* feat1 = (const float*)d_in[0];
    const float* feat2 = (const float*)d_in[1];
    float* out = (float*)d_out;
    cudaFuncSetAttribute(corr_leaky_kernel,
                         cudaFuncAttributeMaxDynamicSharedMemorySize, SMEM_BYTES);
    reset_ctr_kernel<<<1, 1>>>();
    corr_leaky_kernel<<<NBLOCKS, NTHREADS, SMEM_BYTES>>>(feat1, feat2, out);
}

// round 14
// speedup vs baseline: 1.8505x; 1.8505x over previous
#include <cuda_runtime.h>

// PWC-Net correlation (MAX_DISP=4 -> 81 channels) + LeakyReLU(0.1), /C normalize.
// feat1, feat2: [N=8, C=256, H=80, W=160] fp32. out: [N, 81, H, W] fp32.
//
// R10 (best 213us): occ3 persistent + cp.async double-buffer + b-streaming.
// R12 FAILED (384us): f1 via __ldg -> 540 LDG/SM/phase x 4cyc LSU floor > phase
//      budget. f1 must stay smem-staged; scalar LDG in inner loop forbidden.
// R13: barrier batching. s1 gets 2 batch-buffers of 4 chunks (20.5KB), s2 stays
//      2-buffer warp-private. __syncthreads only every 4 chunks (64 -> 16 per
//      row); intra-batch phases sync with wait_group+__syncwarp. s1 batch
//      visibility: writers issue post-barrier, wait own group next phase, and
//      readers start only after the NEXT boundary barrier.

#define MAXD 4
#define DD   9
#define NCH  81
#define C_   256
#define H_   80
#define W_   160
#define N_   8
#define HW_  (H_ * W_)
#define NROWS (N_ * H_)
#define CC   4
#define P_   5
#define F2W  (W_ + 2*MAXD)   // 168
#define NQ4  (F2W / 4)       // 42
#define NTHREADS (DD * 32)   // 288
#define NCHUNK (C_ / CC)     // 64
#define BATCH 4              // chunks per s1 batch
#define NBATCH (NCHUNK / BATCH)  // 16
#define NBLOCKS (148 * 3)    // 444 persistent blocks, 3 CTAs/SM

#define S1_FLOATS (2 * BATCH * CC * W_)     // 5120
#define S2_FLOATS (2 * CC * DD * F2W)       // 12096
#define SMEM_BYTES ((S1_FLOATS + S2_FLOATS) * 4)  // 68864 B -> 206.6KB/SM occ3

__device__ int g_row_ctr;
__global__ void reset_ctr_kernel() { g_row_ctr = 0; }

__device__ __forceinline__ void cp16(float* dst_smem, const float* src_gmem) {
    unsigned d = (unsigned)__cvta_generic_to_shared(dst_smem);
    asm volatile("cp.async.cg.shared.global [%0], [%1], 16;" :: "r"(d), "l"(src_gmem));
}
#define CP_COMMIT() asm volatile("cp.async.commit_group;")
#define CP_WAIT0()  asm volatile("cp.async.wait_group 0;" ::: "memory")

__global__ __launch_bounds__(NTHREADS, 3)
void corr_leaky_kernel(const float* __restrict__ f1,
                       const float* __restrict__ f2,
                       float* __restrict__ out)
{
    extern __shared__ __align__(16) float smem[];
    float* s1 = smem;               // [2][BATCH][CC][W_]
    float* s2 = smem + S1_FLOATS;   // [2][CC][DD][F2W]
#define S1REF(kb2,s,c,x) s1[((((kb2)*BATCH + (s))*CC + (c))*W_) + (x)]
#define S2REF(b,c,r,j)   s2[(((b)*CC + (c))*DD + (r))*F2W + (j)]
    __shared__ int s_row;

    const int tid  = threadIdx.x;
    const int dy   = tid >> 5;
    const int lane = tid & 31;
    const int x0   = lane * P_;

    const float scale = 1.0f / (float)C_;

    for (;;) {
        if (tid == 0) s_row = atomicAdd(&g_row_ctr, 1);
        __syncthreads();
        const int row = s_row;       // end-of-row barrier orders next rewrite
        if (row >= NROWS) break;

        const int n = row / H_;
        const int y = row - n * H_;

        const int img_base = n * C_ * HW_;
        const int  gy    = y + dy - MAXD;
        const bool rowok = ((unsigned)gy < (unsigned)H_);
        const float* f1base = f1 + img_base + y * W_;
        const float* f2base = f2 + img_base + gy * W_;

        // pad slots (fixed borders) of this warp's s2 rows, both buffers
        if (rowok) {
            const float4 z4 = make_float4(0.f, 0.f, 0.f, 0.f);
#pragma unroll
            for (int b = 0; b < 2; b++)
#pragma unroll
                for (int c = 0; c < CC; c++) {
                    if (lane == 0) *(float4*)&S2REF(b, c, dy, 0) = z4;
                    if (lane == 1) *(float4*)&S2REF(b, c, dy, 4 * (NQ4 - 1)) = z4;
                }
        }

        float acc[P_][DD];
#pragma unroll
        for (int p = 0; p < P_; p++)
#pragma unroll
            for (int dx = 0; dx < DD; dx++) acc[p][dx] = 0.0f;

        // ---- prologue: stage s1 batch 0 + s2 chunk 0 ----
        for (int q = tid; q < BATCH * CC * (W_ / 4); q += NTHREADS) {
            const int s   = q / (CC * (W_ / 4));
            const int rem = q - s * (CC * (W_ / 4));
            const int c   = rem / (W_ / 4);
            const int j4  = rem - c * (W_ / 4);
            cp16(&S1REF(0, s, c, 4 * j4), f1base + (s * CC + c) * HW_ + 4 * j4);
        }
        if (rowok) {
#pragma unroll
            for (int c = 0; c < CC; c++) {
                const float* rowp = f2base + c * HW_;
                if (lane >= 1) cp16(&S2REF(0, c, dy, 4 * lane),        rowp + 4 * lane - 4);
                if (lane <= 8) cp16(&S2REF(0, c, dy, 4 * (32 + lane)), rowp + 4 * (32 + lane) - 4);
            }
        }
        CP_COMMIT();

#pragma unroll 4
        for (int i = 0; i < NCHUNK; i++) {
            const int cur = i & 1;            // compile-time under unroll 4
            CP_WAIT0();                        // own groups done (s2 + any s1 part)
            if ((i & 3) == 0) {
                __syncthreads();               // batch boundary: publish s1 batch i/4
                const int kb = i >> 2;
                if (kb + 1 < NBATCH) {         // stage s1 batch kb+1 (parity (kb+1)&1)
                    const int cbase = (kb + 1) * BATCH * CC;
                    for (int q = tid; q < BATCH * CC * (W_ / 4); q += NTHREADS) {
                        const int s   = q / (CC * (W_ / 4));
                        const int rem = q - s * (CC * (W_ / 4));
                        const int c   = rem / (W_ / 4);
                        const int j4  = rem - c * (W_ / 4);
                        cp16(&S1REF((kb + 1) & 1, s, c, 4 * j4),
                             f1base + (cbase + s * CC + c) * HW_ + 4 * j4);
                    }
                }
            } else {
                __syncwarp();                  // s2 warp-private publish
            }

            if (i + 1 < NCHUNK && rowok) {     // stage s2 chunk i+1
                const int nb = cur ^ 1;
                const int c0 = (i + 1) * CC;
#pragma unroll
                for (int c = 0; c < CC; c++) {
                    const float* rowp = f2base + (c0 + c) * HW_;
                    if (lane >= 1) cp16(&S2REF(nb, c, dy, 4 * lane),        rowp + 4 * lane - 4);
                    if (lane <= 8) cp16(&S2REF(nb, c, dy, 4 * (32 + lane)), rowp + 4 * (32 + lane) - 4);
                }
            }
            CP_COMMIT();                       // empty group OK on last iter/!rowok

            // compute chunk i (skip for out-of-range rows: acc stays 0)
            if (rowok) {
                const int kb2 = (i >> 2) & 1;
                const int slt = i & 3;         // compile-time under unroll 4
#pragma unroll
                for (int cc = 0; cc < CC; cc++) {
                    const float* s1row = &S1REF(kb2, slt, cc, x0);
                    const float* s2row = &S2REF(cur, cc, dy, x0);
                    float a[P_];
#pragma unroll
                    for (int p = 0; p < P_; p++) a[p] = s1row[p];
#pragma unroll
                    for (int k = 0; k < P_ + DD - 1; k++) {
                        const float bk = s2row[k];
                        const int plo = (k - (DD - 1)) > 0 ? (k - (DD - 1)) : 0;
                        const int phi = k < (P_ - 1) ? k : (P_ - 1);
#pragma unroll
                        for (int p = plo; p <= phi; p++)
                            acc[p][k - p] = fmaf(a[p], bk, acc[p][k - p]);
                    }
                }
            }
        }

        // epilogue: /C, LeakyReLU(0.1), store (acc=0 -> 0 for !rowok warps)
        const int out_base = n * NCH * HW_ + y * W_;
#pragma unroll
        for (int dx = 0; dx < DD; dx++) {
            const int ch = dy * DD + dx;
            float* orow = out + out_base + ch * HW_;
#pragma unroll
            for (int p = 0; p < P_; p++) {
                float v = acc[p][dx] * scale;
                v = (v > 0.0f) ? v : 0.1f * v;
                orow[x0 + p] = v;
            }
        }

        __syncthreads();   // all reads done before smem rebind / s_row rewrite
    }
}

extern "C" void kernel_launch(void* const* d_in, const int* in_sizes, int n_in,
                              void* d_out, int out_size)
{
    const float* feat1 = (const float*)d_in[0];
    const float* feat2 = (const float*)d_in[1];
    float* out = (float*)d_out;
    cudaFuncSetAttribute(corr_leaky_kernel,
                         cudaFuncAttributeMaxDynamicSharedMemorySize, SMEM_BYTES);
    reset_ctr_kernel<<<1, 1>>>();
    corr_leaky_kernel<<<NBLOCKS, NTHREADS, SMEM_BYTES>>>(feat1, feat2, out);
}